// round 9
// baseline (speedup 1.0000x reference)
#include <cuda_runtime.h>

// Persistent-hidden-state fused RNN + MLP.
// Each CTA owns ROWS=64 batch rows; h (64x256 fp32) lives in SMEM (stored
// transposed [k][row]) across all T=79 backward steps. U (256x256) is streamed
// from L2 in double-buffered 16-row tiles each step. Inner product uses
// packed fp32x2 FMA (fma.rn.f32x2) for 2x fp32 throughput on sm_103a.

#define T_STEPS 79
#define F_IN    8
#define C_DIM   256
#define ROWS    64
#define KTILE   16
#define NTILES  16          // C_DIM / KTILE
#define THREADS 256

typedef unsigned long long ull;

__device__ __forceinline__ void ffma2(ull& d, ull a, ull b) {
    asm("fma.rn.f32x2 %0, %1, %2, %0;" : "+l"(d) : "l"(a), "l"(b));
}
__device__ __forceinline__ ull bcast2(float a) {
    ull r; asm("mov.b64 %0, {%1, %1};" : "=l"(r) : "f"(a)); return r;
}
__device__ __forceinline__ float2 unpack2(ull v) {
    float2 f; asm("mov.b64 {%0, %1}, %2;" : "=f"(f.x), "=f"(f.y) : "l"(v)); return f;
}

// One k-step of the outer-product GEMM: acc[8 rows][4 col-pairs] +=
// h[k][8 rows] (broadcast-packed) * M[k][8 cols] (packed pairs).
__device__ __forceinline__ void micro_step(const float* hrow, const ull* urow,
                                           ull acc[8][4]) {
    float4 ha = *(const float4*)(hrow);
    float4 hb = *(const float4*)(hrow + 4);
    ull u0 = urow[0], u1 = urow[1], u2 = urow[2], u3 = urow[3];
    float hv[8] = {ha.x, ha.y, ha.z, ha.w, hb.x, hb.y, hb.z, hb.w};
#pragma unroll
    for (int ri = 0; ri < 8; ++ri) {
        ull a2 = bcast2(hv[ri]);
        ffma2(acc[ri][0], a2, u0);
        ffma2(acc[ri][1], a2, u1);
        ffma2(acc[ri][2], a2, u2);
        ffma2(acc[ri][3], a2, u3);
    }
}

// acc += h_s(ROWS x 256, layout [k][ROWS]) @ M (256x256 row-major in gmem),
// streaming M through a double-buffered SMEM tile (16 rows x 256 cols).
__device__ __forceinline__ void gemm_acc(const float* __restrict__ M,
                                         float* U_s, const float* h_s,
                                         int tid, int tr, int tc,
                                         ull acc[8][4]) {
    // preload tile 0
#pragma unroll
    for (int j = 0; j < 4; ++j)
        ((float4*)U_s)[tid + j * THREADS] = ((const float4*)M)[tid + j * THREADS];
    __syncthreads();
    int buf = 0;
#pragma unroll 1
    for (int kt = 0; kt < NTILES; ++kt) {
        float4 pre[4];
        if (kt + 1 < NTILES) {
            const float4* src = (const float4*)(M + (kt + 1) * (KTILE * C_DIM));
#pragma unroll
            for (int j = 0; j < 4; ++j) pre[j] = src[tid + j * THREADS];
        }
        const float* Ub = U_s + buf * (KTILE * C_DIM);
#pragma unroll
        for (int k = 0; k < KTILE; ++k) {
            micro_step(h_s + (kt * KTILE + k) * ROWS + tr * 8,
                       (const ull*)(Ub + k * C_DIM + tc * 8), acc);
        }
        if (kt + 1 < NTILES) {
            float* dst = U_s + (buf ^ 1) * (KTILE * C_DIM);
#pragma unroll
            for (int j = 0; j < 4; ++j)
                ((float4*)dst)[tid + j * THREADS] = pre[j];
            __syncthreads();
            buf ^= 1;
        }
    }
}

__global__ void __launch_bounds__(THREADS, 2)
rnn_mlp_kernel(const float* __restrict__ x, const float* __restrict__ W,
               const float* __restrict__ U, const float* __restrict__ bias,
               const float* __restrict__ W1, const float* __restrict__ b1,
               float* __restrict__ out) {
    extern __shared__ float smem[];
    float* U_s  = smem;                          // 2*16*256   = 8192 f
    float* h_s  = U_s + 2 * KTILE * C_DIM;       // 256*64     = 16384 f
    float* x_s  = h_s + C_DIM * ROWS;            // 8*64       = 512 f
    float* W_s  = x_s + F_IN * ROWS;             // 8*256      = 2048 f
    float* b_s  = W_s + F_IN * C_DIM;            // 256 f
    float* b1_s = b_s + C_DIM;                   // 256 f

    const int tid  = threadIdx.x;
    const int tr   = tid & 7;    // row block: rows tr*8 .. tr*8+7
    const int tc   = tid >> 3;   // col block: cols tc*8 .. tc*8+7
    const int row0 = blockIdx.x * ROWS;

    // Stage W, b, b1 into SMEM; zero h.
    for (int i = tid; i < (F_IN * C_DIM) / 4; i += THREADS)
        ((float4*)W_s)[i] = ((const float4*)W)[i];
    if (tid < 64)       ((float4*)b_s)[tid]       = ((const float4*)bias)[tid];
    else if (tid < 128) ((float4*)b1_s)[tid - 64] = ((const float4*)b1)[tid - 64];
    for (int i = tid; i < (C_DIM * ROWS) / 4; i += THREADS)
        ((float4*)h_s)[i] = make_float4(0.f, 0.f, 0.f, 0.f);
    __syncthreads();

    const float* xb = x + (size_t)row0 * (T_STEPS * F_IN);

    // go_backwards: process timesteps T-1 down to 0.
    for (int t = T_STEPS - 1; t >= 0; --t) {
        // Stage x_t transposed: x_s[f*ROWS + r] = x[row0+r][t][f]
        if (tid < 128) {
            int r = tid >> 1, q = tid & 1;
            float4 v = *(const float4*)(xb + (size_t)r * (T_STEPS * F_IN)
                                        + t * F_IN + q * 4);
            x_s[(q * 4 + 0) * ROWS + r] = v.x;
            x_s[(q * 4 + 1) * ROWS + r] = v.y;
            x_s[(q * 4 + 2) * ROWS + r] = v.z;
            x_s[(q * 4 + 3) * ROWS + r] = v.w;
        }
        __syncthreads();   // x_s ready; h_s writes from prev step already synced

        // acc = b + x_t @ W
        ull acc[8][4];
        {
            const ull* b2 = (const ull*)(b_s + tc * 8);
            ull v0 = b2[0], v1 = b2[1], v2 = b2[2], v3 = b2[3];
#pragma unroll
            for (int ri = 0; ri < 8; ++ri) {
                acc[ri][0] = v0; acc[ri][1] = v1;
                acc[ri][2] = v2; acc[ri][3] = v3;
            }
#pragma unroll
            for (int f = 0; f < F_IN; ++f)
                micro_step(x_s + f * ROWS + tr * 8,
                           (const ull*)(W_s + f * C_DIM + tc * 8), acc);
        }

        // acc += h @ U
        gemm_acc(U, U_s, h_s, tid, tr, tc, acc);

        __syncthreads();   // all threads done reading h_s

        // h = relu(acc), written transposed [c][r] with vectorized stores.
#pragma unroll
        for (int cj = 0; cj < 4; ++cj) {
            float2 p0 = unpack2(acc[0][cj]), p1 = unpack2(acc[1][cj]);
            float2 p2 = unpack2(acc[2][cj]), p3 = unpack2(acc[3][cj]);
            float2 p4 = unpack2(acc[4][cj]), p5 = unpack2(acc[5][cj]);
            float2 p6 = unpack2(acc[6][cj]), p7 = unpack2(acc[7][cj]);
            int c0 = tc * 8 + cj * 2;
            float* d0 = h_s + c0 * ROWS + tr * 8;
            float* d1 = d0 + ROWS;
            *(float4*)d0       = make_float4(fmaxf(p0.x, 0.f), fmaxf(p1.x, 0.f),
                                             fmaxf(p2.x, 0.f), fmaxf(p3.x, 0.f));
            *(float4*)(d0 + 4) = make_float4(fmaxf(p4.x, 0.f), fmaxf(p5.x, 0.f),
                                             fmaxf(p6.x, 0.f), fmaxf(p7.x, 0.f));
            *(float4*)d1       = make_float4(fmaxf(p0.y, 0.f), fmaxf(p1.y, 0.f),
                                             fmaxf(p2.y, 0.f), fmaxf(p3.y, 0.f));
            *(float4*)(d1 + 4) = make_float4(fmaxf(p4.y, 0.f), fmaxf(p5.y, 0.f),
                                             fmaxf(p6.y, 0.f), fmaxf(p7.y, 0.f));
        }
        __syncthreads();
    }

    // Final dense: out = relu(h_last @ W1 + b1)
    ull acc[8][4];
    {
        const ull* b2 = (const ull*)(b1_s + tc * 8);
        ull v0 = b2[0], v1 = b2[1], v2 = b2[2], v3 = b2[3];
#pragma unroll
        for (int ri = 0; ri < 8; ++ri) {
            acc[ri][0] = v0; acc[ri][1] = v1;
            acc[ri][2] = v2; acc[ri][3] = v3;
        }
    }
    gemm_acc(W1, U_s, h_s, tid, tr, tc, acc);

    float* orow = out + (size_t)row0 * C_DIM + tc * 8;
#pragma unroll
    for (int ri = 0; ri < 8; ++ri) {
        float2 q0 = unpack2(acc[ri][0]), q1 = unpack2(acc[ri][1]);
        float2 q2 = unpack2(acc[ri][2]), q3 = unpack2(acc[ri][3]);
        float4 v0 = make_float4(fmaxf(q0.x, 0.f), fmaxf(q0.y, 0.f),
                                fmaxf(q1.x, 0.f), fmaxf(q1.y, 0.f));
        float4 v1 = make_float4(fmaxf(q2.x, 0.f), fmaxf(q2.y, 0.f),
                                fmaxf(q3.x, 0.f), fmaxf(q3.y, 0.f));
        float* p = orow + (size_t)(tr * 8 + ri) * C_DIM;
        *(float4*)p       = v0;
        *(float4*)(p + 4) = v1;
    }
}

extern "C" void kernel_launch(void* const* d_in, const int* in_sizes, int n_in,
                              void* d_out, int out_size) {
    const float* x  = (const float*)d_in[0];
    const float* W  = (const float*)d_in[1];
    const float* U  = (const float*)d_in[2];
    const float* b  = (const float*)d_in[3];
    const float* W1 = (const float*)d_in[4];
    const float* b1 = (const float*)d_in[5];
    float* out = (float*)d_out;

    int Btot = in_sizes[0] / (T_STEPS * F_IN);   // 65536
    int grid = Btot / ROWS;                      // 1024

    size_t shmem = (size_t)(2 * KTILE * C_DIM + C_DIM * ROWS + F_IN * ROWS +
                            F_IN * C_DIM + 2 * C_DIM) * sizeof(float); // 110592 B
    cudaFuncSetAttribute(rnn_mlp_kernel,
                         cudaFuncAttributeMaxDynamicSharedMemorySize, (int)shmem);
    rnn_mlp_kernel<<<grid, THREADS, shmem>>>(x, W, U, b, W1, b1, out);
}

// round 10
// speedup vs baseline: 1.0004x; 1.0004x over previous
#include <cuda_runtime.h>

// Persistent-hidden-state fused RNN + MLP.
// Each CTA owns ROWS=64 batch rows; h (64x256 fp32) lives in SMEM (stored
// transposed [k][row]) across all T=79 backward steps. U (256x256) is streamed
// from L2 in double-buffered 16-row tiles each step. Inner product uses
// packed fp32x2 FMA (fma.rn.f32x2) for 2x fp32 throughput on sm_103a.

#define T_STEPS 79
#define F_IN    8
#define C_DIM   256
#define ROWS    64
#define KTILE   16
#define NTILES  16          // C_DIM / KTILE
#define THREADS 256

typedef unsigned long long ull;

__device__ __forceinline__ void ffma2(ull& d, ull a, ull b) {
    asm("fma.rn.f32x2 %0, %1, %2, %0;" : "+l"(d) : "l"(a), "l"(b));
}
__device__ __forceinline__ ull bcast2(float a) {
    ull r; asm("mov.b64 %0, {%1, %1};" : "=l"(r) : "f"(a)); return r;
}
__device__ __forceinline__ float2 unpack2(ull v) {
    float2 f; asm("mov.b64 {%0, %1}, %2;" : "=f"(f.x), "=f"(f.y) : "l"(v)); return f;
}

// One k-step of the outer-product GEMM: acc[8 rows][4 col-pairs] +=
// h[k][8 rows] (broadcast-packed) * M[k][8 cols] (packed pairs).
__device__ __forceinline__ void micro_step(const float* hrow, const ull* urow,
                                           ull acc[8][4]) {
    float4 ha = *(const float4*)(hrow);
    float4 hb = *(const float4*)(hrow + 4);
    ull u0 = urow[0], u1 = urow[1], u2 = urow[2], u3 = urow[3];
    float hv[8] = {ha.x, ha.y, ha.z, ha.w, hb.x, hb.y, hb.z, hb.w};
#pragma unroll
    for (int ri = 0; ri < 8; ++ri) {
        ull a2 = bcast2(hv[ri]);
        ffma2(acc[ri][0], a2, u0);
        ffma2(acc[ri][1], a2, u1);
        ffma2(acc[ri][2], a2, u2);
        ffma2(acc[ri][3], a2, u3);
    }
}

// acc += h_s(ROWS x 256, layout [k][ROWS]) @ M (256x256 row-major in gmem),
// streaming M through a double-buffered SMEM tile (16 rows x 256 cols).
__device__ __forceinline__ void gemm_acc(const float* __restrict__ M,
                                         float* U_s, const float* h_s,
                                         int tid, int tr, int tc,
                                         ull acc[8][4]) {
    // preload tile 0
#pragma unroll
    for (int j = 0; j < 4; ++j)
        ((float4*)U_s)[tid + j * THREADS] = ((const float4*)M)[tid + j * THREADS];
    __syncthreads();
    int buf = 0;
#pragma unroll 1
    for (int kt = 0; kt < NTILES; ++kt) {
        float4 pre[4];
        if (kt + 1 < NTILES) {
            const float4* src = (const float4*)(M + (kt + 1) * (KTILE * C_DIM));
#pragma unroll
            for (int j = 0; j < 4; ++j) pre[j] = src[tid + j * THREADS];
        }
        const float* Ub = U_s + buf * (KTILE * C_DIM);
#pragma unroll
        for (int k = 0; k < KTILE; ++k) {
            micro_step(h_s + (kt * KTILE + k) * ROWS + tr * 8,
                       (const ull*)(Ub + k * C_DIM + tc * 8), acc);
        }
        if (kt + 1 < NTILES) {
            float* dst = U_s + (buf ^ 1) * (KTILE * C_DIM);
#pragma unroll
            for (int j = 0; j < 4; ++j)
                ((float4*)dst)[tid + j * THREADS] = pre[j];
            __syncthreads();
            buf ^= 1;
        }
    }
}

__global__ void __launch_bounds__(THREADS, 2)
rnn_mlp_kernel(const float* __restrict__ x, const float* __restrict__ W,
               const float* __restrict__ U, const float* __restrict__ bias,
               const float* __restrict__ W1, const float* __restrict__ b1,
               float* __restrict__ out) {
    extern __shared__ float smem[];
    float* U_s  = smem;                          // 2*16*256   = 8192 f
    float* h_s  = U_s + 2 * KTILE * C_DIM;       // 256*64     = 16384 f
    float* x_s  = h_s + C_DIM * ROWS;            // 8*64       = 512 f
    float* W_s  = x_s + F_IN * ROWS;             // 8*256      = 2048 f
    float* b_s  = W_s + F_IN * C_DIM;            // 256 f
    float* b1_s = b_s + C_DIM;                   // 256 f

    const int tid  = threadIdx.x;
    const int tr   = tid & 7;    // row block: rows tr*8 .. tr*8+7
    const int tc   = tid >> 3;   // col block: cols tc*8 .. tc*8+7
    const int row0 = blockIdx.x * ROWS;

    // Stage W, b, b1 into SMEM; zero h.
    for (int i = tid; i < (F_IN * C_DIM) / 4; i += THREADS)
        ((float4*)W_s)[i] = ((const float4*)W)[i];
    if (tid < 64)       ((float4*)b_s)[tid]       = ((const float4*)bias)[tid];
    else if (tid < 128) ((float4*)b1_s)[tid - 64] = ((const float4*)b1)[tid - 64];
    for (int i = tid; i < (C_DIM * ROWS) / 4; i += THREADS)
        ((float4*)h_s)[i] = make_float4(0.f, 0.f, 0.f, 0.f);
    __syncthreads();

    const float* xb = x + (size_t)row0 * (T_STEPS * F_IN);

    // go_backwards: process timesteps T-1 down to 0.
    for (int t = T_STEPS - 1; t >= 0; --t) {
        // Stage x_t transposed: x_s[f*ROWS + r] = x[row0+r][t][f]
        if (tid < 128) {
            int r = tid >> 1, q = tid & 1;
            float4 v = *(const float4*)(xb + (size_t)r * (T_STEPS * F_IN)
                                        + t * F_IN + q * 4);
            x_s[(q * 4 + 0) * ROWS + r] = v.x;
            x_s[(q * 4 + 1) * ROWS + r] = v.y;
            x_s[(q * 4 + 2) * ROWS + r] = v.z;
            x_s[(q * 4 + 3) * ROWS + r] = v.w;
        }
        __syncthreads();   // x_s ready; h_s writes from prev step already synced

        // acc = b + x_t @ W
        ull acc[8][4];
        {
            const ull* b2 = (const ull*)(b_s + tc * 8);
            ull v0 = b2[0], v1 = b2[1], v2 = b2[2], v3 = b2[3];
#pragma unroll
            for (int ri = 0; ri < 8; ++ri) {
                acc[ri][0] = v0; acc[ri][1] = v1;
                acc[ri][2] = v2; acc[ri][3] = v3;
            }
#pragma unroll
            for (int f = 0; f < F_IN; ++f)
                micro_step(x_s + f * ROWS + tr * 8,
                           (const ull*)(W_s + f * C_DIM + tc * 8), acc);
        }

        // acc += h @ U
        gemm_acc(U, U_s, h_s, tid, tr, tc, acc);

        __syncthreads();   // all threads done reading h_s

        // h = relu(acc), written transposed [c][r] with vectorized stores.
#pragma unroll
        for (int cj = 0; cj < 4; ++cj) {
            float2 p0 = unpack2(acc[0][cj]), p1 = unpack2(acc[1][cj]);
            float2 p2 = unpack2(acc[2][cj]), p3 = unpack2(acc[3][cj]);
            float2 p4 = unpack2(acc[4][cj]), p5 = unpack2(acc[5][cj]);
            float2 p6 = unpack2(acc[6][cj]), p7 = unpack2(acc[7][cj]);
            int c0 = tc * 8 + cj * 2;
            float* d0 = h_s + c0 * ROWS + tr * 8;
            float* d1 = d0 + ROWS;
            *(float4*)d0       = make_float4(fmaxf(p0.x, 0.f), fmaxf(p1.x, 0.f),
                                             fmaxf(p2.x, 0.f), fmaxf(p3.x, 0.f));
            *(float4*)(d0 + 4) = make_float4(fmaxf(p4.x, 0.f), fmaxf(p5.x, 0.f),
                                             fmaxf(p6.x, 0.f), fmaxf(p7.x, 0.f));
            *(float4*)d1       = make_float4(fmaxf(p0.y, 0.f), fmaxf(p1.y, 0.f),
                                             fmaxf(p2.y, 0.f), fmaxf(p3.y, 0.f));
            *(float4*)(d1 + 4) = make_float4(fmaxf(p4.y, 0.f), fmaxf(p5.y, 0.f),
                                             fmaxf(p6.y, 0.f), fmaxf(p7.y, 0.f));
        }
        __syncthreads();
    }

    // Final dense: out = relu(h_last @ W1 + b1)
    ull acc[8][4];
    {
        const ull* b2 = (const ull*)(b1_s + tc * 8);
        ull v0 = b2[0], v1 = b2[1], v2 = b2[2], v3 = b2[3];
#pragma unroll
        for (int ri = 0; ri < 8; ++ri) {
            acc[ri][0] = v0; acc[ri][1] = v1;
            acc[ri][2] = v2; acc[ri][3] = v3;
        }
    }
    gemm_acc(W1, U_s, h_s, tid, tr, tc, acc);

    float* orow = out + (size_t)row0 * C_DIM + tc * 8;
#pragma unroll
    for (int ri = 0; ri < 8; ++ri) {
        float2 q0 = unpack2(acc[ri][0]), q1 = unpack2(acc[ri][1]);
        float2 q2 = unpack2(acc[ri][2]), q3 = unpack2(acc[ri][3]);
        float4 v0 = make_float4(fmaxf(q0.x, 0.f), fmaxf(q0.y, 0.f),
                                fmaxf(q1.x, 0.f), fmaxf(q1.y, 0.f));
        float4 v1 = make_float4(fmaxf(q2.x, 0.f), fmaxf(q2.y, 0.f),
                                fmaxf(q3.x, 0.f), fmaxf(q3.y, 0.f));
        float* p = orow + (size_t)(tr * 8 + ri) * C_DIM;
        *(float4*)p       = v0;
        *(float4*)(p + 4) = v1;
    }
}

extern "C" void kernel_launch(void* const* d_in, const int* in_sizes, int n_in,
                              void* d_out, int out_size) {
    const float* x  = (const float*)d_in[0];
    const float* W  = (const float*)d_in[1];
    const float* U  = (const float*)d_in[2];
    const float* b  = (const float*)d_in[3];
    const float* W1 = (const float*)d_in[4];
    const float* b1 = (const float*)d_in[5];
    float* out = (float*)d_out;

    int Btot = in_sizes[0] / (T_STEPS * F_IN);   // 65536
    int grid = Btot / ROWS;                      // 1024

    size_t shmem = (size_t)(2 * KTILE * C_DIM + C_DIM * ROWS + F_IN * ROWS +
                            F_IN * C_DIM + 2 * C_DIM) * sizeof(float); // 110592 B
    cudaFuncSetAttribute(rnn_mlp_kernel,
                         cudaFuncAttributeMaxDynamicSharedMemorySize, (int)shmem);
    rnn_mlp_kernel<<<grid, THREADS, shmem>>>(x, W, U, b, W1, b1, out);
}

// round 11
// speedup vs baseline: 1.0011x; 1.0007x over previous
#include <cuda_runtime.h>

// Persistent-hidden-state fused RNN + MLP.
// Each CTA owns ROWS=64 batch rows; h (64x256 fp32) lives in SMEM (stored
// transposed [k][row]) across all T=79 backward steps. U (256x256) is streamed
// from L2 in double-buffered 16-row tiles each step. Inner product uses
// packed fp32x2 FMA (fma.rn.f32x2) for 2x fp32 throughput on sm_103a.

#define T_STEPS 79
#define F_IN    8
#define C_DIM   256
#define ROWS    64
#define KTILE   16
#define NTILES  16          // C_DIM / KTILE
#define THREADS 256

typedef unsigned long long ull;

__device__ __forceinline__ void ffma2(ull& d, ull a, ull b) {
    asm("fma.rn.f32x2 %0, %1, %2, %0;" : "+l"(d) : "l"(a), "l"(b));
}
__device__ __forceinline__ ull bcast2(float a) {
    ull r; asm("mov.b64 %0, {%1, %1};" : "=l"(r) : "f"(a)); return r;
}
__device__ __forceinline__ float2 unpack2(ull v) {
    float2 f; asm("mov.b64 {%0, %1}, %2;" : "=f"(f.x), "=f"(f.y) : "l"(v)); return f;
}

// One k-step of the outer-product GEMM: acc[8 rows][4 col-pairs] +=
// h[k][8 rows] (broadcast-packed) * M[k][8 cols] (packed pairs).
__device__ __forceinline__ void micro_step(const float* hrow, const ull* urow,
                                           ull acc[8][4]) {
    float4 ha = *(const float4*)(hrow);
    float4 hb = *(const float4*)(hrow + 4);
    ull u0 = urow[0], u1 = urow[1], u2 = urow[2], u3 = urow[3];
    float hv[8] = {ha.x, ha.y, ha.z, ha.w, hb.x, hb.y, hb.z, hb.w};
#pragma unroll
    for (int ri = 0; ri < 8; ++ri) {
        ull a2 = bcast2(hv[ri]);
        ffma2(acc[ri][0], a2, u0);
        ffma2(acc[ri][1], a2, u1);
        ffma2(acc[ri][2], a2, u2);
        ffma2(acc[ri][3], a2, u3);
    }
}

// acc += h_s(ROWS x 256, layout [k][ROWS]) @ M (256x256 row-major in gmem),
// streaming M through a double-buffered SMEM tile (16 rows x 256 cols).
__device__ __forceinline__ void gemm_acc(const float* __restrict__ M,
                                         float* U_s, const float* h_s,
                                         int tid, int tr, int tc,
                                         ull acc[8][4]) {
    // preload tile 0
#pragma unroll
    for (int j = 0; j < 4; ++j)
        ((float4*)U_s)[tid + j * THREADS] = ((const float4*)M)[tid + j * THREADS];
    __syncthreads();
    int buf = 0;
#pragma unroll 1
    for (int kt = 0; kt < NTILES; ++kt) {
        float4 pre[4];
        if (kt + 1 < NTILES) {
            const float4* src = (const float4*)(M + (kt + 1) * (KTILE * C_DIM));
#pragma unroll
            for (int j = 0; j < 4; ++j) pre[j] = src[tid + j * THREADS];
        }
        const float* Ub = U_s + buf * (KTILE * C_DIM);
#pragma unroll
        for (int k = 0; k < KTILE; ++k) {
            micro_step(h_s + (kt * KTILE + k) * ROWS + tr * 8,
                       (const ull*)(Ub + k * C_DIM + tc * 8), acc);
        }
        if (kt + 1 < NTILES) {
            float* dst = U_s + (buf ^ 1) * (KTILE * C_DIM);
#pragma unroll
            for (int j = 0; j < 4; ++j)
                ((float4*)dst)[tid + j * THREADS] = pre[j];
            __syncthreads();
            buf ^= 1;
        }
    }
}

__global__ void __launch_bounds__(THREADS, 2)
rnn_mlp_kernel(const float* __restrict__ x, const float* __restrict__ W,
               const float* __restrict__ U, const float* __restrict__ bias,
               const float* __restrict__ W1, const float* __restrict__ b1,
               float* __restrict__ out) {
    extern __shared__ float smem[];
    float* U_s  = smem;                          // 2*16*256   = 8192 f
    float* h_s  = U_s + 2 * KTILE * C_DIM;       // 256*64     = 16384 f
    float* x_s  = h_s + C_DIM * ROWS;            // 8*64       = 512 f
    float* W_s  = x_s + F_IN * ROWS;             // 8*256      = 2048 f
    float* b_s  = W_s + F_IN * C_DIM;            // 256 f
    float* b1_s = b_s + C_DIM;                   // 256 f

    const int tid  = threadIdx.x;
    const int tr   = tid & 7;    // row block: rows tr*8 .. tr*8+7
    const int tc   = tid >> 3;   // col block: cols tc*8 .. tc*8+7
    const int row0 = blockIdx.x * ROWS;

    // Stage W, b, b1 into SMEM; zero h.
    for (int i = tid; i < (F_IN * C_DIM) / 4; i += THREADS)
        ((float4*)W_s)[i] = ((const float4*)W)[i];
    if (tid < 64)       ((float4*)b_s)[tid]       = ((const float4*)bias)[tid];
    else if (tid < 128) ((float4*)b1_s)[tid - 64] = ((const float4*)b1)[tid - 64];
    for (int i = tid; i < (C_DIM * ROWS) / 4; i += THREADS)
        ((float4*)h_s)[i] = make_float4(0.f, 0.f, 0.f, 0.f);
    __syncthreads();

    const float* xb = x + (size_t)row0 * (T_STEPS * F_IN);

    // go_backwards: process timesteps T-1 down to 0.
    for (int t = T_STEPS - 1; t >= 0; --t) {
        // Stage x_t transposed: x_s[f*ROWS + r] = x[row0+r][t][f]
        if (tid < 128) {
            int r = tid >> 1, q = tid & 1;
            float4 v = *(const float4*)(xb + (size_t)r * (T_STEPS * F_IN)
                                        + t * F_IN + q * 4);
            x_s[(q * 4 + 0) * ROWS + r] = v.x;
            x_s[(q * 4 + 1) * ROWS + r] = v.y;
            x_s[(q * 4 + 2) * ROWS + r] = v.z;
            x_s[(q * 4 + 3) * ROWS + r] = v.w;
        }
        __syncthreads();   // x_s ready; h_s writes from prev step already synced

        // acc = b + x_t @ W
        ull acc[8][4];
        {
            const ull* b2 = (const ull*)(b_s + tc * 8);
            ull v0 = b2[0], v1 = b2[1], v2 = b2[2], v3 = b2[3];
#pragma unroll
            for (int ri = 0; ri < 8; ++ri) {
                acc[ri][0] = v0; acc[ri][1] = v1;
                acc[ri][2] = v2; acc[ri][3] = v3;
            }
#pragma unroll
            for (int f = 0; f < F_IN; ++f)
                micro_step(x_s + f * ROWS + tr * 8,
                           (const ull*)(W_s + f * C_DIM + tc * 8), acc);
        }

        // acc += h @ U
        gemm_acc(U, U_s, h_s, tid, tr, tc, acc);

        __syncthreads();   // all threads done reading h_s

        // h = relu(acc), written transposed [c][r] with vectorized stores.
#pragma unroll
        for (int cj = 0; cj < 4; ++cj) {
            float2 p0 = unpack2(acc[0][cj]), p1 = unpack2(acc[1][cj]);
            float2 p2 = unpack2(acc[2][cj]), p3 = unpack2(acc[3][cj]);
            float2 p4 = unpack2(acc[4][cj]), p5 = unpack2(acc[5][cj]);
            float2 p6 = unpack2(acc[6][cj]), p7 = unpack2(acc[7][cj]);
            int c0 = tc * 8 + cj * 2;
            float* d0 = h_s + c0 * ROWS + tr * 8;
            float* d1 = d0 + ROWS;
            *(float4*)d0       = make_float4(fmaxf(p0.x, 0.f), fmaxf(p1.x, 0.f),
                                             fmaxf(p2.x, 0.f), fmaxf(p3.x, 0.f));
            *(float4*)(d0 + 4) = make_float4(fmaxf(p4.x, 0.f), fmaxf(p5.x, 0.f),
                                             fmaxf(p6.x, 0.f), fmaxf(p7.x, 0.f));
            *(float4*)d1       = make_float4(fmaxf(p0.y, 0.f), fmaxf(p1.y, 0.f),
                                             fmaxf(p2.y, 0.f), fmaxf(p3.y, 0.f));
            *(float4*)(d1 + 4) = make_float4(fmaxf(p4.y, 0.f), fmaxf(p5.y, 0.f),
                                             fmaxf(p6.y, 0.f), fmaxf(p7.y, 0.f));
        }
        __syncthreads();
    }

    // Final dense: out = relu(h_last @ W1 + b1)
    ull acc[8][4];
    {
        const ull* b2 = (const ull*)(b1_s + tc * 8);
        ull v0 = b2[0], v1 = b2[1], v2 = b2[2], v3 = b2[3];
#pragma unroll
        for (int ri = 0; ri < 8; ++ri) {
            acc[ri][0] = v0; acc[ri][1] = v1;
            acc[ri][2] = v2; acc[ri][3] = v3;
        }
    }
    gemm_acc(W1, U_s, h_s, tid, tr, tc, acc);

    float* orow = out + (size_t)row0 * C_DIM + tc * 8;
#pragma unroll
    for (int ri = 0; ri < 8; ++ri) {
        float2 q0 = unpack2(acc[ri][0]), q1 = unpack2(acc[ri][1]);
        float2 q2 = unpack2(acc[ri][2]), q3 = unpack2(acc[ri][3]);
        float4 v0 = make_float4(fmaxf(q0.x, 0.f), fmaxf(q0.y, 0.f),
                                fmaxf(q1.x, 0.f), fmaxf(q1.y, 0.f));
        float4 v1 = make_float4(fmaxf(q2.x, 0.f), fmaxf(q2.y, 0.f),
                                fmaxf(q3.x, 0.f), fmaxf(q3.y, 0.f));
        float* p = orow + (size_t)(tr * 8 + ri) * C_DIM;
        *(float4*)p       = v0;
        *(float4*)(p + 4) = v1;
    }
}

extern "C" void kernel_launch(void* const* d_in, const int* in_sizes, int n_in,
                              void* d_out, int out_size) {
    const float* x  = (const float*)d_in[0];
    const float* W  = (const float*)d_in[1];
    const float* U  = (const float*)d_in[2];
    const float* b  = (const float*)d_in[3];
    const float* W1 = (const float*)d_in[4];
    const float* b1 = (const float*)d_in[5];
    float* out = (float*)d_out;

    int Btot = in_sizes[0] / (T_STEPS * F_IN);   // 65536
    int grid = Btot / ROWS;                      // 1024

    size_t shmem = (size_t)(2 * KTILE * C_DIM + C_DIM * ROWS + F_IN * ROWS +
                            F_IN * C_DIM + 2 * C_DIM) * sizeof(float); // 110592 B
    cudaFuncSetAttribute(rnn_mlp_kernel,
                         cudaFuncAttributeMaxDynamicSharedMemorySize, (int)shmem);
    rnn_mlp_kernel<<<grid, THREADS, shmem>>>(x, W, U, b, W1, b1, out);
}